// round 9
// baseline (speedup 1.0000x reference)
#include <cuda_runtime.h>
#include <cstdint>

#define Bz  2
#define T_  2048
#define BT  4096
#define D_  1024
#define H_  16
#define HD_ 64
#define L_  4
#define V_  32000
#define FF_ 4096

// ---------------- scratch (static device memory; no allocations) ----------
__device__ float g_x [BT * D_];
__device__ float g_h [BT * D_];
__device__ float g_q [BT * D_];
__device__ float g_k [BT * D_];
__device__ float g_v [BT * D_];
__device__ float g_ao[BT * D_];
__device__ float g_ff[BT * FF_];

// ---------------- embedding ----------------------------------------------
__global__ void embed_kernel(const int* __restrict__ ctx,
                             const float4* __restrict__ tok,
                             const float4* __restrict__ pos)
{
    int i   = blockIdx.x * 256 + threadIdx.x;
    int row = i / (D_ / 4);
    int c   = i - row * (D_ / 4);
    int t   = row & (T_ - 1);
    float4 a = tok[(size_t)ctx[row] * (D_ / 4) + c];
    float4 b = pos[(size_t)t * (D_ / 4) + c];
    ((float4*)g_x)[i] = make_float4(a.x + b.x, a.y + b.y, a.z + b.z, a.w + b.w);
}

// ---------------- layernorm ----------------------------------------------
__global__ void ln_kernel(const float* __restrict__ in,
                          const float* __restrict__ gamma,
                          const float* __restrict__ beta,
                          float* __restrict__ out)
{
    int row = blockIdx.x;
    const float4* r4 = (const float4*)(in + (size_t)row * D_);
    float4 v = r4[threadIdx.x];
    float s  = v.x + v.y + v.z + v.w;
    float ss = v.x * v.x + v.y * v.y + v.z * v.z + v.w * v.w;
    #pragma unroll
    for (int o = 16; o > 0; o >>= 1) {
        s  += __shfl_xor_sync(0xffffffffu, s,  o);
        ss += __shfl_xor_sync(0xffffffffu, ss, o);
    }
    __shared__ float shs[8], shss[8];
    int w = threadIdx.x >> 5, lane = threadIdx.x & 31;
    if (lane == 0) { shs[w] = s; shss[w] = ss; }
    __syncthreads();
    float ts = 0.f, tss = 0.f;
    #pragma unroll
    for (int i = 0; i < 8; i++) { ts += shs[i]; tss += shss[i]; }
    float mean = ts * (1.0f / D_);
    float var  = tss * (1.0f / D_) - mean * mean;
    float inv  = rsqrtf(var + 1e-5f);
    float4 g  = ((const float4*)gamma)[threadIdx.x];
    float4 bb = ((const float4*)beta)[threadIdx.x];
    float4 o;
    o.x = (v.x - mean) * inv * g.x + bb.x;
    o.y = (v.y - mean) * inv * g.y + bb.y;
    o.z = (v.z - mean) * inv * g.z + bb.z;
    o.w = (v.w - mean) * inv * g.w + bb.w;
    ((float4*)(out + (size_t)row * D_))[threadIdx.x] = o;
}

// ---------------- TF32 helpers --------------------------------------------
__device__ __forceinline__ uint32_t f2tf(float f)
{
    uint32_t r;
    asm("cvt.rna.tf32.f32 %0, %1;" : "=r"(r) : "f"(f));
    return r;
}

__device__ __forceinline__ void mma8(float* c, const uint32_t* a, const uint32_t* b)
{
    asm volatile(
        "mma.sync.aligned.m16n8k8.row.col.f32.tf32.tf32.f32 "
        "{%0,%1,%2,%3}, {%4,%5,%6,%7}, {%8,%9}, {%0,%1,%2,%3};"
        : "+f"(c[0]), "+f"(c[1]), "+f"(c[2]), "+f"(c[3])
        : "r"(a[0]), "r"(a[1]), "r"(a[2]), "r"(a[3]), "r"(b[0]), "r"(b[1]));
}

// ---------------- TF32 tensor-core GEMM ------------------------------------
#define GBM 128
#define GBN 128
#define GBK 32
#define AFS 4096
#define BROW 136
#define BFS (GBK * BROW)
#define GEMM_SMEM ((2 * AFS + 2 * BFS) * 4)

template <int EPI>
__device__ __forceinline__ void
gemm_core(const float* __restrict__ A, const float* __restrict__ W,
          const float* __restrict__ bias, const float* __restrict__ res,
          float* __restrict__ C, int M, int N, int K)
{
    extern __shared__ uint32_t smu[];
    uint32_t* AF = smu;
    uint32_t (*Bs)[GBK][BROW] = (uint32_t(*)[GBK][BROW])(smu + 2 * AFS);

    const int tid  = threadIdx.x;
    const int wid  = tid >> 5, lane = tid & 31;
    const int gid  = lane >> 2, tig = lane & 3;
    const int wmi  = wid & 1;
    const int wn   = (wid >> 1) * 32;
    const int bm   = blockIdx.y * GBM;
    const int bn   = blockIdx.x * GBN;
    const int K4   = K >> 2, N4 = N >> 2;

    float acc[4][4][4];
    #pragma unroll
    for (int i = 0; i < 4; i++)
        #pragma unroll
        for (int j = 0; j < 4; j++)
            #pragma unroll
            for (int r = 0; r < 4; r++) acc[i][j][r] = 0.f;

    float4 ra[4], rb[4];

    #define GLOAD(k0)                                                        \
        do {                                                                 \
            _Pragma("unroll")                                                \
            for (int t = 0; t < 4; t++) {                                    \
                int idx = tid + t * 256;                                     \
                int r = idx >> 3, c = idx & 7;                               \
                ra[t] = ((const float4*)A)[(size_t)(bm + r) * K4 + ((k0) >> 2) + c]; \
            }                                                                \
            _Pragma("unroll")                                                \
            for (int t = 0; t < 4; t++) {                                    \
                int idx = tid + t * 256;                                     \
                int r = idx >> 5, c = idx & 31;                              \
                rb[t] = ((const float4*)W)[(size_t)((k0) + r) * N4 + (bn >> 2) + c]; \
            }                                                                \
        } while (0)

    #define SSTORE(st)                                                       \
        do {                                                                 \
            _Pragma("unroll")                                                \
            for (int t = 0; t < 4; t++) {                                    \
                int idx = tid + t * 256;                                     \
                int r = idx >> 3, c = idx & 7;                               \
                int awmi = r >> 6, rr = r & 63;                              \
                int mt = rr >> 4, rh = (rr >> 3) & 1, agid = rr & 7;         \
                int ks = c >> 1, reg = rh + 2 * (c & 1);                     \
                uint32_t* p = AF + (st) * AFS +                              \
                              (((awmi * 4 + ks) * 4 + mt) << 7) + reg;       \
                float fv[4] = {ra[t].x, ra[t].y, ra[t].z, ra[t].w};          \
                _Pragma("unroll")                                            \
                for (int j = 0; j < 4; j++)                                  \
                    p[(((agid * 4 + j) ^ ks) << 2)] = f2tf(fv[j]);           \
            }                                                                \
            _Pragma("unroll")                                                \
            for (int t = 0; t < 4; t++) {                                    \
                int idx = tid + t * 256;                                     \
                int r = idx >> 5, c = idx & 31;                              \
                uint4 u;                                                     \
                u.x = f2tf(rb[t].x); u.y = f2tf(rb[t].y);                    \
                u.z = f2tf(rb[t].z); u.w = f2tf(rb[t].w);                    \
                *(uint4*)&Bs[st][r][c * 4] = u;                              \
            }                                                                \
        } while (0)

    GLOAD(0);
    SSTORE(0);
    __syncthreads();

    const int niter = K / GBK;
    int st = 0;
    for (int it = 0; it < niter; it++) {
        if (it + 1 < niter) GLOAD((it + 1) * GBK);

        const uint32_t* Awarp = AF + st * AFS + (wmi << 11);
        #pragma unroll
        for (int ks = 0; ks < 4; ks++) {
            uint32_t af[4][4], bf[4][2];
            int ls = ((lane ^ ks) << 2);
            #pragma unroll
            for (int mt = 0; mt < 4; mt++) {
                uint4 a4 = *(const uint4*)(Awarp + ((ks * 4 + mt) << 7) + ls);
                af[mt][0] = a4.x; af[mt][1] = a4.y;
                af[mt][2] = a4.z; af[mt][3] = a4.w;
            }
            #pragma unroll
            for (int nt = 0; nt < 4; nt++) {
                bf[nt][0] = Bs[st][ks * 8 + tig][wn + nt * 8 + gid];
                bf[nt][1] = Bs[st][ks * 8 + tig + 4][wn + nt * 8 + gid];
            }
            #pragma unroll
            for (int mt = 0; mt < 4; mt++)
                #pragma unroll
                for (int nt = 0; nt < 4; nt++)
                    mma8(acc[mt][nt], af[mt], bf[nt]);
        }

        if (it + 1 < niter) {
            SSTORE(st ^ 1);
            __syncthreads();
            st ^= 1;
        }
    }

    const int wm = wmi * 64;
    #pragma unroll
    for (int mt = 0; mt < 4; mt++) {
        #pragma unroll
        for (int half = 0; half < 2; half++) {
            int m = bm + wm + mt * 16 + gid + half * 8;
            #pragma unroll
            for (int nt = 0; nt < 4; nt++) {
                int n = bn + wn + nt * 8 + tig * 2;
                float2 v;
                v.x = acc[mt][nt][half * 2 + 0];
                v.y = acc[mt][nt][half * 2 + 1];
                if (EPI & 1) { v.x += bias[n]; v.y += bias[n + 1]; }
                if (EPI & 2) { v.x = fmaxf(v.x, 0.f); v.y = fmaxf(v.y, 0.f); }
                if (EPI & 4) {
                    float2 r = *(const float2*)&res[(size_t)m * N + n];
                    v.x += r.x; v.y += r.y;
                }
                *(float2*)&C[(size_t)m * N + n] = v;
            }
        }
    }
    #undef GLOAD
    #undef SSTORE
}

template <int EPI>
__global__ void __launch_bounds__(256)
gemm_tc(const float* __restrict__ A, const float* __restrict__ W,
        const float* __restrict__ bias, const float* __restrict__ res,
        float* __restrict__ C, int M, int N, int K)
{
    gemm_core<EPI>(A, W, bias, res, C, M, N, K);
}

struct QKVArgs { const float *w0, *w1, *w2; float *c0, *c1, *c2; };

__global__ void __launch_bounds__(256)
gemm_qkv(const float* __restrict__ A, QKVArgs p, int M, int N, int K)
{
    const float* W = (blockIdx.z == 0) ? p.w0 : (blockIdx.z == 1) ? p.w1 : p.w2;
    float*       C = (blockIdx.z == 0) ? p.c0 : (blockIdx.z == 1) ? p.c1 : p.c2;
    gemm_core<0>(A, W, nullptr, nullptr, C, M, N, K);
}

// ---------------- TF32 tensor-core causal flash attention ------------------
// 64x64 tiles, HD=64. 8 warps: 4(m) x 2(n). S in split-tf32 (3 mma), PV plain.
#define AQS 68                       // padded row stride (floats)
#define ATILE (64 * AQS)             // 4352
#define ATTN_SMEM ((6 * ATILE + 3 * 64 + 2 * 256) * 4)

__global__ void __launch_bounds__(256) attn_tc_kernel()
{
    int qi = blockIdx.x, h = blockIdx.y, b = blockIdx.z;
    extern __shared__ float sma[];
    uint32_t* QH = (uint32_t*)sma;                 // [64][AQS] tf32 hi
    uint32_t* QL = QH + ATILE;                     // tf32 lo
    uint32_t* KH = QH + 2 * ATILE;
    uint32_t* KL = QH + 3 * ATILE;
    uint32_t* VT = QH + 4 * ATILE;                 // V^T [e][c]
    float*    SS = sma + 5 * ATILE;                // [64][AQS] scores / probs
    float*    MR = sma + 6 * ATILE;                // 64
    float*    LR = MR + 64;
    float*    AR = MR + 128;
    float*    PM = MR + 192;                       // 256 partial max
    float*    PS = PM + 256;                       // 256 partial sum

    const int tid = threadIdx.x;
    const int lane = tid & 31, wid = tid >> 5;
    const int gid = lane >> 2, tig = lane & 3;
    const int r0  = (wid & 3) * 16;                // warp m-rows
    const int n0s = (wid >> 2) * 32;               // warp n-cols

    // load Q (hi/lo split)
    for (int i = tid; i < 64 * 64; i += 256) {
        int r = i >> 6, e = i & 63;
        float f = g_q[(size_t)(b * T_ + (qi << 6) + r) * D_ + h * HD_ + e];
        uint32_t hi = f2tf(f);
        QH[r * AQS + e] = hi;
        QL[r * AQS + e] = f2tf(f - __uint_as_float(hi));
    }
    if (tid < 64) { MR[tid] = -1e30f; LR[tid] = 0.f; }

    float oacc[4][4];
    #pragma unroll
    for (int i = 0; i < 4; i++)
        #pragma unroll
        for (int j = 0; j < 4; j++) oacc[i][j] = 0.f;

    for (int kt = 0; kt <= qi; kt++) {
        __syncthreads();
        for (int i = tid; i < 64 * 64; i += 256) {
            int c = i >> 6, e = i & 63;
            size_t g = (size_t)(b * T_ + (kt << 6) + c) * D_ + h * HD_ + e;
            float kf = g_k[g];
            uint32_t khi = f2tf(kf);
            KH[c * AQS + e] = khi;
            KL[c * AQS + e] = f2tf(kf - __uint_as_float(khi));
            VT[e * AQS + c] = f2tf(g_v[g]);
        }
        __syncthreads();

        // ---- S = Q K^T  (split tf32: hi*hi + lo*hi + hi*lo)
        float sa[4][4];
        #pragma unroll
        for (int i = 0; i < 4; i++)
            #pragma unroll
            for (int j = 0; j < 4; j++) sa[i][j] = 0.f;

        #pragma unroll
        for (int ks = 0; ks < 8; ks++) {
            int kk = ks * 8 + tig;
            uint32_t aH[4], aL[4];
            aH[0] = QH[(r0 + gid) * AQS + kk];     aH[1] = QH[(r0 + gid + 8) * AQS + kk];
            aH[2] = QH[(r0 + gid) * AQS + kk + 4]; aH[3] = QH[(r0 + gid + 8) * AQS + kk + 4];
            aL[0] = QL[(r0 + gid) * AQS + kk];     aL[1] = QL[(r0 + gid + 8) * AQS + kk];
            aL[2] = QL[(r0 + gid) * AQS + kk + 4]; aL[3] = QL[(r0 + gid + 8) * AQS + kk + 4];
            #pragma unroll
            for (int nt = 0; nt < 4; nt++) {
                int nn = n0s + nt * 8 + gid;
                uint32_t bH[2] = { KH[nn * AQS + kk], KH[nn * AQS + kk + 4] };
                uint32_t bL[2] = { KL[nn * AQS + kk], KL[nn * AQS + kk + 4] };
                mma8(sa[nt], aH, bH);
                mma8(sa[nt], aL, bH);
                mma8(sa[nt], aH, bL);
            }
        }

        // ---- scale, mask, store S
        {
            bool diag = (kt == qi);
            int ra = r0 + gid, rb = ra + 8;
            #pragma unroll
            for (int nt = 0; nt < 4; nt++) {
                int cb = n0s + nt * 8 + tig * 2;
                float v0 = sa[nt][0] * 0.125f, v1 = sa[nt][1] * 0.125f;
                float v2 = sa[nt][2] * 0.125f, v3 = sa[nt][3] * 0.125f;
                if (diag) {
                    if (cb     > ra) v0 = -1e30f;
                    if (cb + 1 > ra) v1 = -1e30f;
                    if (cb     > rb) v2 = -1e30f;
                    if (cb + 1 > rb) v3 = -1e30f;
                }
                *(float2*)&SS[ra * AQS + cb] = make_float2(v0, v1);
                *(float2*)&SS[rb * AQS + cb] = make_float2(v2, v3);
            }
        }
        __syncthreads();

        // ---- softmax (4 threads per row)
        {
            int r = tid & 63, qd = tid >> 6;
            const float* row = SS + r * AQS + qd * 16;
            float mx = -1e30f;
            #pragma unroll
            for (int j = 0; j < 16; j++) mx = fmaxf(mx, row[j]);
            PM[qd * 64 + r] = mx;
        }
        __syncthreads();
        if (tid < 64) {
            int r = tid;
            float mo = MR[r];
            float mn = fmaxf(fmaxf(PM[r], PM[64 + r]), fmaxf(PM[128 + r], PM[192 + r]));
            mn = fmaxf(mn, mo);
            MR[r] = mn;
            AR[r] = __expf(mo - mn);
        }
        __syncthreads();
        {
            int r = tid & 63, qd = tid >> 6;
            float mn = MR[r];
            float* row = SS + r * AQS + qd * 16;
            float s = 0.f;
            #pragma unroll
            for (int j = 0; j < 16; j++) {
                float p = __expf(row[j] - mn);
                row[j] = p;
                s += p;
            }
            PS[qd * 64 + r] = s;
        }
        __syncthreads();
        if (tid < 64) {
            int r = tid;
            LR[r] = LR[r] * AR[r] + PS[r] + PS[64 + r] + PS[128 + r] + PS[192 + r];
        }

        // ---- O = O*alpha + P V
        {
            float a0 = AR[r0 + gid], a1 = AR[r0 + gid + 8];
            #pragma unroll
            for (int nt = 0; nt < 4; nt++) {
                oacc[nt][0] *= a0; oacc[nt][1] *= a0;
                oacc[nt][2] *= a1; oacc[nt][3] *= a1;
            }
            #pragma unroll
            for (int ks = 0; ks < 8; ks++) {
                int kk = ks * 8 + tig;
                uint32_t af[4];
                af[0] = f2tf(SS[(r0 + gid) * AQS + kk]);
                af[1] = f2tf(SS[(r0 + gid + 8) * AQS + kk]);
                af[2] = f2tf(SS[(r0 + gid) * AQS + kk + 4]);
                af[3] = f2tf(SS[(r0 + gid + 8) * AQS + kk + 4]);
                #pragma unroll
                for (int nt = 0; nt < 4; nt++) {
                    int nn = n0s + nt * 8 + gid;
                    uint32_t bf[2] = { VT[nn * AQS + kk], VT[nn * AQS + kk + 4] };
                    mma8(oacc[nt], af, bf);
                }
            }
        }
    }

    __syncthreads();   // LR complete
    {
        float inv0 = 1.0f / LR[r0 + gid], inv1 = 1.0f / LR[r0 + gid + 8];
        #pragma unroll
        for (int nt = 0; nt < 4; nt++) {
            int cb = n0s + nt * 8 + tig * 2;
            size_t b0 = (size_t)(b * T_ + (qi << 6) + r0 + gid) * D_ + h * HD_ + cb;
            size_t b1 = (size_t)(b * T_ + (qi << 6) + r0 + gid + 8) * D_ + h * HD_ + cb;
            *(float2*)&g_ao[b0] = make_float2(oacc[nt][0] * inv0, oacc[nt][1] * inv0);
            *(float2*)&g_ao[b1] = make_float2(oacc[nt][2] * inv1, oacc[nt][3] * inv1);
        }
    }
}

// ---------------- host side ----------------------------------------------
static void launch_gemm(const float* A, const float* W, const float* bias,
                        const float* res, float* C, int M, int N, int K, int epi)
{
    dim3 grid(N / GBN, M / GBM), blk(256);
    switch (epi) {
        case 0: gemm_tc<0><<<grid, blk, GEMM_SMEM>>>(A, W, nullptr, nullptr, C, M, N, K); break;
        case 1: gemm_tc<1><<<grid, blk, GEMM_SMEM>>>(A, W, bias,    nullptr, C, M, N, K); break;
        case 3: gemm_tc<3><<<grid, blk, GEMM_SMEM>>>(A, W, bias,    nullptr, C, M, N, K); break;
        case 5: gemm_tc<5><<<grid, blk, GEMM_SMEM>>>(A, W, bias,    res,     C, M, N, K); break;
    }
}

extern "C" void kernel_launch(void* const* d_in, const int* in_sizes, int n_in,
                              void* d_out, int out_size)
{
    const int*   ctx  = (const int*)  d_in[0];
    const float* tok  = (const float*)d_in[1];
    const float* pos  = (const float*)d_in[2];
    const float* Wq   = (const float*)d_in[3];
    const float* Wk   = (const float*)d_in[4];
    const float* Wv   = (const float*)d_in[5];
    const float* Wo   = (const float*)d_in[6];
    const float* bo   = (const float*)d_in[7];
    const float* ln1s = (const float*)d_in[8];
    const float* ln1b = (const float*)d_in[9];
    const float* W1   = (const float*)d_in[10];
    const float* b1   = (const float*)d_in[11];
    const float* W2   = (const float*)d_in[12];
    const float* b2   = (const float*)d_in[13];
    const float* ln2s = (const float*)d_in[14];
    const float* ln2b = (const float*)d_in[15];
    const float* lnfs = (const float*)d_in[16];
    const float* lnfb = (const float*)d_in[17];
    const float* Wout = (const float*)d_in[18];
    const float* bout = (const float*)d_in[19];
    float* out = (float*)d_out;

    float *x, *h, *q, *k, *v, *ao, *ff;
    cudaGetSymbolAddress((void**)&x,  g_x);
    cudaGetSymbolAddress((void**)&h,  g_h);
    cudaGetSymbolAddress((void**)&q,  g_q);
    cudaGetSymbolAddress((void**)&k,  g_k);
    cudaGetSymbolAddress((void**)&v,  g_v);
    cudaGetSymbolAddress((void**)&ao, g_ao);
    cudaGetSymbolAddress((void**)&ff, g_ff);

    cudaFuncSetAttribute(attn_tc_kernel,
                         cudaFuncAttributeMaxDynamicSharedMemorySize, ATTN_SMEM);
    cudaFuncSetAttribute(gemm_tc<0>, cudaFuncAttributeMaxDynamicSharedMemorySize, GEMM_SMEM);
    cudaFuncSetAttribute(gemm_tc<1>, cudaFuncAttributeMaxDynamicSharedMemorySize, GEMM_SMEM);
    cudaFuncSetAttribute(gemm_tc<3>, cudaFuncAttributeMaxDynamicSharedMemorySize, GEMM_SMEM);
    cudaFuncSetAttribute(gemm_tc<5>, cudaFuncAttributeMaxDynamicSharedMemorySize, GEMM_SMEM);
    cudaFuncSetAttribute(gemm_qkv,   cudaFuncAttributeMaxDynamicSharedMemorySize, GEMM_SMEM);

    embed_kernel<<<BT * D_ / 1024, 256>>>(ctx, (const float4*)tok, (const float4*)pos);

    for (int l = 0; l < L_; l++) {
        ln_kernel<<<BT, 256>>>(x, ln1s + (size_t)l * D_, ln1b + (size_t)l * D_, h);
        QKVArgs p { Wq + (size_t)l * D_ * D_, Wk + (size_t)l * D_ * D_,
                    Wv + (size_t)l * D_ * D_, q, k, v };
        gemm_qkv<<<dim3(D_ / GBN, BT / GBM, 3), 256, GEMM_SMEM>>>(h, p, BT, D_, D_);
        attn_tc_kernel<<<dim3(T_ / 64, H_, Bz), 256, ATTN_SMEM>>>();
        launch_gemm(ao, Wo + (size_t)l * D_ * D_, bo + (size_t)l * D_, x, x, BT, D_, D_, 5);
        ln_kernel<<<BT, 256>>>(x, ln2s + (size_t)l * D_, ln2b + (size_t)l * D_, h);
        launch_gemm(h, W1 + (size_t)l * D_ * FF_, b1 + (size_t)l * FF_, nullptr, ff, BT, FF_, D_, 3);
        launch_gemm(ff, W2 + (size_t)l * FF_ * D_, b2 + (size_t)l * D_, x, x, BT, D_, FF_, 5);
    }
    ln_kernel<<<BT, 256>>>(x, lnfs, lnfb, h);
    launch_gemm(h, Wout, bout, nullptr, out, BT, V_, D_, 1);
}

// round 12
// speedup vs baseline: 1.0175x; 1.0175x over previous
#include <cuda_runtime.h>
#include <cuda_fp16.h>
#include <cstdint>

#define Bz  2
#define T_  2048
#define BT  4096
#define D_  1024
#define H_  16
#define HD_ 64
#define L_  4
#define V_  32000
#define FF_ 4096

// ---------------- scratch (static device memory; no allocations) ----------
__device__ float g_x [BT * D_];
__device__ float g_h [BT * D_];
__device__ float g_q [BT * D_];
__device__ float g_k [BT * D_];
__device__ float g_v [BT * D_];
__device__ float g_ao[BT * D_];
__device__ float g_ff[BT * FF_];

// ---------------- embedding ----------------------------------------------
__global__ void embed_kernel(const int* __restrict__ ctx,
                             const float4* __restrict__ tok,
                             const float4* __restrict__ pos)
{
    int i   = blockIdx.x * 256 + threadIdx.x;
    int row = i / (D_ / 4);
    int c   = i - row * (D_ / 4);
    int t   = row & (T_ - 1);
    float4 a = tok[(size_t)ctx[row] * (D_ / 4) + c];
    float4 b = pos[(size_t)t * (D_ / 4) + c];
    ((float4*)g_x)[i] = make_float4(a.x + b.x, a.y + b.y, a.z + b.z, a.w + b.w);
}

// ---------------- layernorm ----------------------------------------------
__global__ void ln_kernel(const float* __restrict__ in,
                          const float* __restrict__ gamma,
                          const float* __restrict__ beta,
                          float* __restrict__ out)
{
    int row = blockIdx.x;
    const float4* r4 = (const float4*)(in + (size_t)row * D_);
    float4 v = r4[threadIdx.x];
    float s  = v.x + v.y + v.z + v.w;
    float ss = v.x * v.x + v.y * v.y + v.z * v.z + v.w * v.w;
    #pragma unroll
    for (int o = 16; o > 0; o >>= 1) {
        s  += __shfl_xor_sync(0xffffffffu, s,  o);
        ss += __shfl_xor_sync(0xffffffffu, ss, o);
    }
    __shared__ float shs[8], shss[8];
    int w = threadIdx.x >> 5, lane = threadIdx.x & 31;
    if (lane == 0) { shs[w] = s; shss[w] = ss; }
    __syncthreads();
    float ts = 0.f, tss = 0.f;
    #pragma unroll
    for (int i = 0; i < 8; i++) { ts += shs[i]; tss += shss[i]; }
    float mean = ts * (1.0f / D_);
    float var  = tss * (1.0f / D_) - mean * mean;
    float inv  = rsqrtf(var + 1e-5f);
    float4 g  = ((const float4*)gamma)[threadIdx.x];
    float4 bb = ((const float4*)beta)[threadIdx.x];
    float4 o;
    o.x = (v.x - mean) * inv * g.x + bb.x;
    o.y = (v.y - mean) * inv * g.y + bb.y;
    o.z = (v.z - mean) * inv * g.z + bb.z;
    o.w = (v.w - mean) * inv * g.w + bb.w;
    ((float4*)(out + (size_t)row * D_))[threadIdx.x] = o;
}

// ---------------- TF32 / fp16 helpers --------------------------------------
__device__ __forceinline__ uint32_t f2tf(float f)
{
    uint32_t r;
    asm("cvt.rna.tf32.f32 %0, %1;" : "=r"(r) : "f"(f));
    return r;
}

__device__ __forceinline__ uint32_t h2u(__half2 h)
{
    uint32_t u;
    __builtin_memcpy(&u, &h, 4);
    return u;
}

__device__ __forceinline__ void mma8(float* c, const uint32_t* a, const uint32_t* b)
{
    asm volatile(
        "mma.sync.aligned.m16n8k8.row.col.f32.tf32.tf32.f32 "
        "{%0,%1,%2,%3}, {%4,%5,%6,%7}, {%8,%9}, {%0,%1,%2,%3};"
        : "+f"(c[0]), "+f"(c[1]), "+f"(c[2]), "+f"(c[3])
        : "r"(a[0]), "r"(a[1]), "r"(a[2]), "r"(a[3]), "r"(b[0]), "r"(b[1]));
}

__device__ __forceinline__ void mma16h(float* c, const uint32_t* a, const uint32_t* b)
{
    asm volatile(
        "mma.sync.aligned.m16n8k16.row.col.f32.f16.f16.f32 "
        "{%0,%1,%2,%3}, {%4,%5,%6,%7}, {%8,%9}, {%0,%1,%2,%3};"
        : "+f"(c[0]), "+f"(c[1]), "+f"(c[2]), "+f"(c[3])
        : "r"(a[0]), "r"(a[1]), "r"(a[2]), "r"(a[3]), "r"(b[0]), "r"(b[1]));
}

// ---------------- TF32 tensor-core GEMM ------------------------------------
#define GBM 128
#define GBN 128
#define GBK 32
#define AFS 4096
#define BROW 136
#define BFS (GBK * BROW)
#define GEMM_SMEM ((2 * AFS + 2 * BFS) * 4)

template <int EPI>
__device__ __forceinline__ void
gemm_core(const float* __restrict__ A, const float* __restrict__ W,
          const float* __restrict__ bias, const float* __restrict__ res,
          float* __restrict__ C, int M, int N, int K)
{
    extern __shared__ uint32_t smu[];
    uint32_t* AF = smu;
    uint32_t (*Bs)[GBK][BROW] = (uint32_t(*)[GBK][BROW])(smu + 2 * AFS);

    const int tid  = threadIdx.x;
    const int wid  = tid >> 5, lane = tid & 31;
    const int gid  = lane >> 2, tig = lane & 3;
    const int wmi  = wid & 1;
    const int wn   = (wid >> 1) * 32;
    const int bm   = blockIdx.y * GBM;
    const int bn   = blockIdx.x * GBN;
    const int K4   = K >> 2, N4 = N >> 2;

    float acc[4][4][4];
    #pragma unroll
    for (int i = 0; i < 4; i++)
        #pragma unroll
        for (int j = 0; j < 4; j++)
            #pragma unroll
            for (int r = 0; r < 4; r++) acc[i][j][r] = 0.f;

    float4 ra[4], rb[4];

    #define GLOAD(k0)                                                        \
        do {                                                                 \
            _Pragma("unroll")                                                \
            for (int t = 0; t < 4; t++) {                                    \
                int idx = tid + t * 256;                                     \
                int r = idx >> 3, c = idx & 7;                               \
                ra[t] = ((const float4*)A)[(size_t)(bm + r) * K4 + ((k0) >> 2) + c]; \
            }                                                                \
            _Pragma("unroll")                                                \
            for (int t = 0; t < 4; t++) {                                    \
                int idx = tid + t * 256;                                     \
                int r = idx >> 5, c = idx & 31;                              \
                rb[t] = ((const float4*)W)[(size_t)((k0) + r) * N4 + (bn >> 2) + c]; \
            }                                                                \
        } while (0)

    #define SSTORE(st)                                                       \
        do {                                                                 \
            _Pragma("unroll")                                                \
            for (int t = 0; t < 4; t++) {                                    \
                int idx = tid + t * 256;                                     \
                int r = idx >> 3, c = idx & 7;                               \
                int awmi = r >> 6, rr = r & 63;                              \
                int mt = rr >> 4, rh = (rr >> 3) & 1, agid = rr & 7;         \
                int ks = c >> 1, reg = rh + 2 * (c & 1);                     \
                uint32_t* p = AF + (st) * AFS +                              \
                              (((awmi * 4 + ks) * 4 + mt) << 7) + reg;       \
                float fv[4] = {ra[t].x, ra[t].y, ra[t].z, ra[t].w};          \
                _Pragma("unroll")                                            \
                for (int j = 0; j < 4; j++)                                  \
                    p[(((agid * 4 + j) ^ ks) << 2)] = f2tf(fv[j]);           \
            }                                                                \
            _Pragma("unroll")                                                \
            for (int t = 0; t < 4; t++) {                                    \
                int idx = tid + t * 256;                                     \
                int r = idx >> 5, c = idx & 31;                              \
                uint4 u;                                                     \
                u.x = f2tf(rb[t].x); u.y = f2tf(rb[t].y);                    \
                u.z = f2tf(rb[t].z); u.w = f2tf(rb[t].w);                    \
                *(uint4*)&Bs[st][r][c * 4] = u;                              \
            }                                                                \
        } while (0)

    GLOAD(0);
    SSTORE(0);
    __syncthreads();

    const int niter = K / GBK;
    int st = 0;
    for (int it = 0; it < niter; it++) {
        if (it + 1 < niter) GLOAD((it + 1) * GBK);

        const uint32_t* Awarp = AF + st * AFS + (wmi << 11);
        #pragma unroll
        for (int ks = 0; ks < 4; ks++) {
            uint32_t af[4][4], bf[4][2];
            int ls = ((lane ^ ks) << 2);
            #pragma unroll
            for (int mt = 0; mt < 4; mt++) {
                uint4 a4 = *(const uint4*)(Awarp + ((ks * 4 + mt) << 7) + ls);
                af[mt][0] = a4.x; af[mt][1] = a4.y;
                af[mt][2] = a4.z; af[mt][3] = a4.w;
            }
            #pragma unroll
            for (int nt = 0; nt < 4; nt++) {
                bf[nt][0] = Bs[st][ks * 8 + tig][wn + nt * 8 + gid];
                bf[nt][1] = Bs[st][ks * 8 + tig + 4][wn + nt * 8 + gid];
            }
            #pragma unroll
            for (int mt = 0; mt < 4; mt++)
                #pragma unroll
                for (int nt = 0; nt < 4; nt++)
                    mma8(acc[mt][nt], af[mt], bf[nt]);
        }

        if (it + 1 < niter) {
            SSTORE(st ^ 1);
            __syncthreads();
            st ^= 1;
        }
    }

    const int wm = wmi * 64;
    #pragma unroll
    for (int mt = 0; mt < 4; mt++) {
        #pragma unroll
        for (int half = 0; half < 2; half++) {
            int m = bm + wm + mt * 16 + gid + half * 8;
            #pragma unroll
            for (int nt = 0; nt < 4; nt++) {
                int n = bn + wn + nt * 8 + tig * 2;
                float2 v;
                v.x = acc[mt][nt][half * 2 + 0];
                v.y = acc[mt][nt][half * 2 + 1];
                if (EPI & 1) { v.x += bias[n]; v.y += bias[n + 1]; }
                if (EPI & 2) { v.x = fmaxf(v.x, 0.f); v.y = fmaxf(v.y, 0.f); }
                if (EPI & 4) {
                    float2 r = *(const float2*)&res[(size_t)m * N + n];
                    v.x += r.x; v.y += r.y;
                }
                *(float2*)&C[(size_t)m * N + n] = v;
            }
        }
    }
    #undef GLOAD
    #undef SSTORE
}

template <int EPI>
__global__ void __launch_bounds__(256)
gemm_tc(const float* __restrict__ A, const float* __restrict__ W,
        const float* __restrict__ bias, const float* __restrict__ res,
        float* __restrict__ C, int M, int N, int K)
{
    gemm_core<EPI>(A, W, bias, res, C, M, N, K);
}

struct QKVArgs { const float *w0, *w1, *w2; float *c0, *c1, *c2; };

__global__ void __launch_bounds__(256)
gemm_qkv(const float* __restrict__ A, QKVArgs p, int M, int N, int K)
{
    const float* W = (blockIdx.z == 0) ? p.w0 : (blockIdx.z == 1) ? p.w1 : p.w2;
    float*       C = (blockIdx.z == 0) ? p.c0 : (blockIdx.z == 1) ? p.c1 : p.c2;
    gemm_core<0>(A, W, nullptr, nullptr, C, M, N, K);
}

// ---------------- FA2-style tensor-core causal attention -------------------
// Q tile 128 rows/CTA, K tile 64. 8 warps each own m16 rows x all 64 cols.
// S = QK^T split-tf32 (3 mma). Softmax in registers (quad shfl).
// PV in fp16 m16n8k16 (same mantissa as tf32); P stays in registers
// (S c-frag layout == PV a-frag layout).
#define KHS 68     // K smem row stride (words)
#define VPS 72     // V pair smem row stride (words)

__global__ void __launch_bounds__(256) attn_fa2_kernel()
{
    __shared__ uint32_t sKH[64 * KHS];
    __shared__ uint32_t sKL[64 * KHS];
    __shared__ uint32_t sVP[32 * VPS];

    const int qi = (int)gridDim.x - 1 - (int)blockIdx.x;   // big tiles first
    const int h  = blockIdx.y, b = blockIdx.z;
    const int tid = threadIdx.x;
    const int lane = tid & 31, wid = tid >> 5;
    const int gid = lane >> 2, tig = lane & 3;
    const int r0  = wid * 16;
    const int hcol = h * HD_;

    // ---- preload Q fragments (hi/lo split) into registers
    uint32_t qH[8][4], qL[8][4];
    {
        size_t base0 = (size_t)(b * T_ + qi * 128 + r0 + gid) * D_ + hcol;
        size_t base1 = base0 + 8 * (size_t)D_;
        #pragma unroll
        for (int ks = 0; ks < 8; ks++) {
            int kk = ks * 8 + tig;
            float f[4] = { g_q[base0 + kk], g_q[base1 + kk],
                           g_q[base0 + kk + 4], g_q[base1 + kk + 4] };
            #pragma unroll
            for (int j = 0; j < 4; j++) {
                uint32_t hi = f2tf(f[j]);
                qH[ks][j] = hi;
                qL[ks][j] = f2tf(f[j] - __uint_as_float(hi));
            }
        }
    }

    float oacc[8][4];
    #pragma unroll
    for (int i = 0; i < 8; i++)
        #pragma unroll
        for (int j = 0; j < 4; j++) oacc[i][j] = 0.f;

    float m0 = -1e30f, m1 = -1e30f, l0 = 0.f, l1 = 0.f;

    const int row0g = qi * 128 + r0 + gid;    // global rows of this thread
    const int row1g = row0g + 8;
    const int ntk = 2 * qi + 2;

    for (int kt = 0; kt < ntk; kt++) {
        __syncthreads();
        // load K (hi/lo) and V (fp16 pairs over seq)
        for (int i = tid; i < 64 * 64; i += 256) {
            int c = i >> 6, e = i & 63;
            float kf = g_k[(size_t)(b * T_ + kt * 64 + c) * D_ + hcol + e];
            uint32_t hi = f2tf(kf);
            sKH[c * KHS + e] = hi;
            sKL[c * KHS + e] = f2tf(kf - __uint_as_float(hi));
        }
        for (int i = tid; i < 32 * 64; i += 256) {
            int cp = i >> 6, e = i & 63;
            size_t gbase = (size_t)(b * T_ + kt * 64 + 2 * cp) * D_ + hcol + e;
            float v0 = g_v[gbase], v1 = g_v[gbase + D_];
            sVP[cp * VPS + e] = h2u(__floats2half2_rn(v0, v1));
        }
        __syncthreads();

        // ---- S = Q K^T (split tf32)
        float sa[8][4];
        #pragma unroll
        for (int i = 0; i < 8; i++)
            #pragma unroll
            for (int j = 0; j < 4; j++) sa[i][j] = 0.f;

        #pragma unroll
        for (int ks = 0; ks < 8; ks++) {
            int kk = ks * 8 + tig;
            #pragma unroll
            for (int nt = 0; nt < 8; nt++) {
                int n = nt * 8 + gid;
                uint32_t bH[2] = { sKH[n * KHS + kk], sKH[n * KHS + kk + 4] };
                uint32_t bL[2] = { sKL[n * KHS + kk], sKL[n * KHS + kk + 4] };
                mma8(sa[nt], qH[ks], bH);
                mma8(sa[nt], qL[ks], bH);
                mma8(sa[nt], qH[ks], bL);
            }
        }

        // ---- scale + causal mask
        bool diag = (kt >= 2 * qi);
        #pragma unroll
        for (int nt = 0; nt < 8; nt++) {
            int cg = kt * 64 + nt * 8 + tig * 2;
            sa[nt][0] *= 0.125f; sa[nt][1] *= 0.125f;
            sa[nt][2] *= 0.125f; sa[nt][3] *= 0.125f;
            if (diag) {
                if (cg     > row0g) sa[nt][0] = -1e30f;
                if (cg + 1 > row0g) sa[nt][1] = -1e30f;
                if (cg     > row1g) sa[nt][2] = -1e30f;
                if (cg + 1 > row1g) sa[nt][3] = -1e30f;
            }
        }

        // ---- online softmax (registers + quad shfl)
        float mx0 = -1e30f, mx1 = -1e30f;
        #pragma unroll
        for (int nt = 0; nt < 8; nt++) {
            mx0 = fmaxf(mx0, fmaxf(sa[nt][0], sa[nt][1]));
            mx1 = fmaxf(mx1, fmaxf(sa[nt][2], sa[nt][3]));
        }
        mx0 = fmaxf(mx0, __shfl_xor_sync(0xffffffffu, mx0, 1));
        mx0 = fmaxf(mx0, __shfl_xor_sync(0xffffffffu, mx0, 2));
        mx1 = fmaxf(mx1, __shfl_xor_sync(0xffffffffu, mx1, 1));
        mx1 = fmaxf(mx1, __shfl_xor_sync(0xffffffffu, mx1, 2));
        float mn0 = fmaxf(m0, mx0), mn1 = fmaxf(m1, mx1);
        float al0 = __expf(m0 - mn0), al1 = __expf(m1 - mn1);
        m0 = mn0; m1 = mn1;

        float s0 = 0.f, s1 = 0.f;
        uint32_t pf[8][2];
        #pragma unroll
        for (int nt = 0; nt < 8; nt++) {
            float p0 = __expf(sa[nt][0] - mn0);
            float p1 = __expf(sa[nt][1] - mn0);
            float p2 = __expf(sa[nt][2] - mn1);
            float p3 = __expf(sa[nt][3] - mn1);
            s0 += p0 + p1; s1 += p2 + p3;
            pf[nt][0] = h2u(__floats2half2_rn(p0, p1));
            pf[nt][1] = h2u(__floats2half2_rn(p2, p3));
        }
        s0 += __shfl_xor_sync(0xffffffffu, s0, 1);
        s0 += __shfl_xor_sync(0xffffffffu, s0, 2);
        s1 += __shfl_xor_sync(0xffffffffu, s1, 1);
        s1 += __shfl_xor_sync(0xffffffffu, s1, 2);
        l0 = l0 * al0 + s0;
        l1 = l1 * al1 + s1;

        #pragma unroll
        for (int nt = 0; nt < 8; nt++) {
            oacc[nt][0] *= al0; oacc[nt][1] *= al0;
            oacc[nt][2] *= al1; oacc[nt][3] *= al1;
        }

        // ---- O += P V  (fp16 m16n8k16, P from registers)
        #pragma unroll
        for (int ks2 = 0; ks2 < 4; ks2++) {
            uint32_t af[4] = { pf[2 * ks2][0], pf[2 * ks2][1],
                               pf[2 * ks2 + 1][0], pf[2 * ks2 + 1][1] };
            #pragma unroll
            for (int nt = 0; nt < 8; nt++) {
                int n = nt * 8 + gid;
                uint32_t bf[2] = { sVP[(ks2 * 8 + tig) * VPS + n],
                                   sVP[(ks2 * 8 + tig + 4) * VPS + n] };
                mma16h(oacc[nt], af, bf);
            }
        }
    }

    // ---- write O / l
    {
        float inv0 = 1.0f / l0, inv1 = 1.0f / l1;
        size_t b0 = (size_t)(b * T_ + row0g) * D_ + hcol;
        size_t b1 = (size_t)(b * T_ + row1g) * D_ + hcol;
        #pragma unroll
        for (int nt = 0; nt < 8; nt++) {
            int cb = nt * 8 + tig * 2;
            *(float2*)&g_ao[b0 + cb] = make_float2(oacc[nt][0] * inv0, oacc[nt][1] * inv0);
            *(float2*)&g_ao[b1 + cb] = make_float2(oacc[nt][2] * inv1, oacc[nt][3] * inv1);
        }
    }
}

// ---------------- host side ----------------------------------------------
static void launch_gemm(const float* A, const float* W, const float* bias,
                        const float* res, float* C, int M, int N, int K, int epi)
{
    dim3 grid(N / GBN, M / GBM), blk(256);
    switch (epi) {
        case 0: gemm_tc<0><<<grid, blk, GEMM_SMEM>>>(A, W, nullptr, nullptr, C, M, N, K); break;
        case 1: gemm_tc<1><<<grid, blk, GEMM_SMEM>>>(A, W, bias,    nullptr, C, M, N, K); break;
        case 3: gemm_tc<3><<<grid, blk, GEMM_SMEM>>>(A, W, bias,    nullptr, C, M, N, K); break;
        case 5: gemm_tc<5><<<grid, blk, GEMM_SMEM>>>(A, W, bias,    res,     C, M, N, K); break;
    }
}

extern "C" void kernel_launch(void* const* d_in, const int* in_sizes, int n_in,
                              void* d_out, int out_size)
{
    const int*   ctx  = (const int*)  d_in[0];
    const float* tok  = (const float*)d_in[1];
    const float* pos  = (const float*)d_in[2];
    const float* Wq   = (const float*)d_in[3];
    const float* Wk   = (const float*)d_in[4];
    const float* Wv   = (const float*)d_in[5];
    const float* Wo   = (const float*)d_in[6];
    const float* bo   = (const float*)d_in[7];
    const float* ln1s = (const float*)d_in[8];
    const float* ln1b = (const float*)d_in[9];
    const float* W1   = (const float*)d_in[10];
    const float* b1   = (const float*)d_in[11];
    const float* W2   = (const float*)d_in[12];
    const float* b2   = (const float*)d_in[13];
    const float* ln2s = (const float*)d_in[14];
    const float* ln2b = (const float*)d_in[15];
    const float* lnfs = (const float*)d_in[16];
    const float* lnfb = (const float*)d_in[17];
    const float* Wout = (const float*)d_in[18];
    const float* bout = (const float*)d_in[19];
    float* out = (float*)d_out;

    float *x, *h, *q, *k, *v, *ao, *ff;
    cudaGetSymbolAddress((void**)&x,  g_x);
    cudaGetSymbolAddress((void**)&h,  g_h);
    cudaGetSymbolAddress((void**)&q,  g_q);
    cudaGetSymbolAddress((void**)&k,  g_k);
    cudaGetSymbolAddress((void**)&v,  g_v);
    cudaGetSymbolAddress((void**)&ao, g_ao);
    cudaGetSymbolAddress((void**)&ff, g_ff);

    cudaFuncSetAttribute(gemm_tc<0>, cudaFuncAttributeMaxDynamicSharedMemorySize, GEMM_SMEM);
    cudaFuncSetAttribute(gemm_tc<1>, cudaFuncAttributeMaxDynamicSharedMemorySize, GEMM_SMEM);
    cudaFuncSetAttribute(gemm_tc<3>, cudaFuncAttributeMaxDynamicSharedMemorySize, GEMM_SMEM);
    cudaFuncSetAttribute(gemm_tc<5>, cudaFuncAttributeMaxDynamicSharedMemorySize, GEMM_SMEM);
    cudaFuncSetAttribute(gemm_qkv,   cudaFuncAttributeMaxDynamicSharedMemorySize, GEMM_SMEM);

    embed_kernel<<<BT * D_ / 1024, 256>>>(ctx, (const float4*)tok, (const float4*)pos);

    for (int l = 0; l < L_; l++) {
        ln_kernel<<<BT, 256>>>(x, ln1s + (size_t)l * D_, ln1b + (size_t)l * D_, h);
        QKVArgs p { Wq + (size_t)l * D_ * D_, Wk + (size_t)l * D_ * D_,
                    Wv + (size_t)l * D_ * D_, q, k, v };
        gemm_qkv<<<dim3(D_ / GBN, BT / GBM, 3), 256, GEMM_SMEM>>>(h, p, BT, D_, D_);
        attn_fa2_kernel<<<dim3(T_ / 128, H_, Bz), 256>>>();
        launch_gemm(ao, Wo + (size_t)l * D_ * D_, bo + (size_t)l * D_, x, x, BT, D_, D_, 5);
        ln_kernel<<<BT, 256>>>(x, ln2s + (size_t)l * D_, ln2b + (size_t)l * D_, h);
        launch_gemm(h, W1 + (size_t)l * D_ * FF_, b1 + (size_t)l * FF_, nullptr, ff, BT, FF_, D_, 3);
        launch_gemm(ff, W2 + (size_t)l * FF_ * D_, b2 + (size_t)l * D_, x, x, BT, D_, FF_, 5);
    }
    ln_kernel<<<BT, 256>>>(x, lnfs, lnfb, h);
    launch_gemm(h, Wout, bout, nullptr, out, BT, V_, D_, 1);
}

// round 13
// speedup vs baseline: 1.6073x; 1.5796x over previous
#include <cuda_runtime.h>
#include <cuda_fp16.h>
#include <cstdint>

#define Bz  2
#define T_  2048
#define BT  4096
#define D_  1024
#define H_  16
#define HD_ 64
#define L_  4
#define V_  32000
#define FF_ 4096

// ---------------- scratch (static device memory; no allocations) ----------
__device__ float g_x [BT * D_];
__device__ float g_h [BT * D_];
__device__ float g_q [BT * D_];
__device__ float g_k [BT * D_];
__device__ float g_v [BT * D_];
__device__ float g_ao[BT * D_];
__device__ float g_ff[BT * FF_];

// ---------------- embedding ----------------------------------------------
__global__ void embed_kernel(const int* __restrict__ ctx,
                             const float4* __restrict__ tok,
                             const float4* __restrict__ pos)
{
    int i   = blockIdx.x * 256 + threadIdx.x;
    int row = i / (D_ / 4);
    int c   = i - row * (D_ / 4);
    int t   = row & (T_ - 1);
    float4 a = tok[(size_t)ctx[row] * (D_ / 4) + c];
    float4 b = pos[(size_t)t * (D_ / 4) + c];
    ((float4*)g_x)[i] = make_float4(a.x + b.x, a.y + b.y, a.z + b.z, a.w + b.w);
}

// ---------------- layernorm ----------------------------------------------
__global__ void ln_kernel(const float* __restrict__ in,
                          const float* __restrict__ gamma,
                          const float* __restrict__ beta,
                          float* __restrict__ out)
{
    int row = blockIdx.x;
    const float4* r4 = (const float4*)(in + (size_t)row * D_);
    float4 v = r4[threadIdx.x];
    float s  = v.x + v.y + v.z + v.w;
    float ss = v.x * v.x + v.y * v.y + v.z * v.z + v.w * v.w;
    #pragma unroll
    for (int o = 16; o > 0; o >>= 1) {
        s  += __shfl_xor_sync(0xffffffffu, s,  o);
        ss += __shfl_xor_sync(0xffffffffu, ss, o);
    }
    __shared__ float shs[8], shss[8];
    int w = threadIdx.x >> 5, lane = threadIdx.x & 31;
    if (lane == 0) { shs[w] = s; shss[w] = ss; }
    __syncthreads();
    float ts = 0.f, tss = 0.f;
    #pragma unroll
    for (int i = 0; i < 8; i++) { ts += shs[i]; tss += shss[i]; }
    float mean = ts * (1.0f / D_);
    float var  = tss * (1.0f / D_) - mean * mean;
    float inv  = rsqrtf(var + 1e-5f);
    float4 g  = ((const float4*)gamma)[threadIdx.x];
    float4 bb = ((const float4*)beta)[threadIdx.x];
    float4 o;
    o.x = (v.x - mean) * inv * g.x + bb.x;
    o.y = (v.y - mean) * inv * g.y + bb.y;
    o.z = (v.z - mean) * inv * g.z + bb.z;
    o.w = (v.w - mean) * inv * g.w + bb.w;
    ((float4*)(out + (size_t)row * D_))[threadIdx.x] = o;
}

// ---------------- fp16 helpers --------------------------------------------
__device__ __forceinline__ uint32_t h2u(__half2 h)
{
    uint32_t u;
    __builtin_memcpy(&u, &h, 4);
    return u;
}

__device__ __forceinline__ void mma16h(float* c, const uint32_t* a, const uint32_t* b)
{
    asm volatile(
        "mma.sync.aligned.m16n8k16.row.col.f32.f16.f16.f32 "
        "{%0,%1,%2,%3}, {%4,%5,%6,%7}, {%8,%9}, {%0,%1,%2,%3};"
        : "+f"(c[0]), "+f"(c[1]), "+f"(c[2]), "+f"(c[3])
        : "r"(a[0]), "r"(a[1]), "r"(a[2]), "r"(a[3]), "r"(b[0]), "r"(b[1]));
}

// ---------------- fp16 tensor-core GEMM ------------------------------------
// C = epi(A[M,K] @ W[K,N]); EPI bit0:+bias  bit1:relu  bit2:+res
// smem words are half2 (2 consecutive k per word). 32-K tile = 16 k-pairs.
#define GBM 128
#define GBN 128
#define GBK 32
#define AFS2 2048            // A frag words per stage: 2*2*4*32*4
#define BROW2 136            // B row stride (words), bank-permuting pad
#define BFS2 (16 * BROW2)
#define GEMM_SMEM ((2 * AFS2 + 2 * BFS2) * 4)

template <int EPI>
__device__ __forceinline__ void
gemm_core(const float* __restrict__ A, const float* __restrict__ W,
          const float* __restrict__ bias, const float* __restrict__ res,
          float* __restrict__ C, int M, int N, int K)
{
    extern __shared__ uint32_t smu[];
    uint32_t* AF = smu;                                      // [2][AFS2]
    uint32_t (*Bs)[16][BROW2] = (uint32_t(*)[16][BROW2])(smu + 2 * AFS2);

    const int tid  = threadIdx.x;
    const int wid  = tid >> 5, lane = tid & 31;
    const int gid  = lane >> 2, tig = lane & 3;
    const int wmi  = wid & 1;                 // warp tile 64x32
    const int wn   = (wid >> 1) * 32;
    const int bm   = blockIdx.y * GBM;
    const int bn   = blockIdx.x * GBN;
    const int K4   = K >> 2, N4 = N >> 2, bn4 = bn >> 2;

    float acc[4][4][4];
    #pragma unroll
    for (int i = 0; i < 4; i++)
        #pragma unroll
        for (int j = 0; j < 4; j++)
            #pragma unroll
            for (int r = 0; r < 4; r++) acc[i][j][r] = 0.f;

    float4 ra[4], rb0[2], rb1[2];

    #define GLOAD(k0)                                                        \
        do {                                                                 \
            _Pragma("unroll")                                                \
            for (int t = 0; t < 4; t++) {                                    \
                int idx = tid + t * 256;                                     \
                int r = idx >> 3, c = idx & 7;                               \
                ra[t] = ((const float4*)A)[(size_t)(bm + r) * K4 + ((k0) >> 2) + c]; \
            }                                                                \
            _Pragma("unroll")                                                \
            for (int t = 0; t < 2; t++) {                                    \
                int idx = tid + t * 256;                                     \
                int kpr = idx >> 5, c = idx & 31;                            \
                rb0[t] = ((const float4*)W)[(size_t)((k0) + 2 * kpr) * N4 + bn4 + c];     \
                rb1[t] = ((const float4*)W)[(size_t)((k0) + 2 * kpr + 1) * N4 + bn4 + c]; \
            }                                                                \
        } while (0)

    // A -> fragment-major fp16 layout AF[wmi][ks2][mt][lane][word]
    #define SSTORE(st)                                                       \
        do {                                                                 \
            _Pragma("unroll")                                                \
            for (int t = 0; t < 4; t++) {                                    \
                int idx = tid + t * 256;                                     \
                int r = idx >> 3, c = idx & 7;                               \
                int awmi = r >> 6, rr = r & 63;                              \
                int mt = rr >> 4, rh = (rr >> 3) & 1, agid = rr & 7;         \
                uint32_t w0 = h2u(__floats2half2_rn(ra[t].x, ra[t].y));      \
                uint32_t w1 = h2u(__floats2half2_rn(ra[t].z, ra[t].w));      \
                _Pragma("unroll")                                            \
                for (int kk = 0; kk < 2; kk++) {                             \
                    int kw = 2 * c + kk;                                     \
                    int ks2 = kw >> 3, p = kw & 7;                           \
                    int tg = p & 3, wsel = p >> 2;                           \
                    AF[(st) * AFS2 +                                         \
                       ((((awmi * 2 + ks2) * 4 + mt) * 32 +                  \
                         (agid * 4 + tg)) << 2) + (wsel * 2 + rh)]           \
                        = kk ? w1 : w0;                                      \
                }                                                            \
            }                                                                \
            _Pragma("unroll")                                                \
            for (int t = 0; t < 2; t++) {                                    \
                int idx = tid + t * 256;                                     \
                int kpr = idx >> 5, c = idx & 31;                            \
                uint4 u;                                                     \
                u.x = h2u(__floats2half2_rn(rb0[t].x, rb1[t].x));            \
                u.y = h2u(__floats2half2_rn(rb0[t].y, rb1[t].y));            \
                u.z = h2u(__floats2half2_rn(rb0[t].z, rb1[t].z));            \
                u.w = h2u(__floats2half2_rn(rb0[t].w, rb1[t].w));            \
                *(uint4*)&Bs[st][kpr][c * 4] = u;                            \
            }                                                                \
        } while (0)

    GLOAD(0);
    SSTORE(0);
    __syncthreads();

    const int niter = K / GBK;
    int st = 0;
    for (int it = 0; it < niter; it++) {
        if (it + 1 < niter) GLOAD((it + 1) * GBK);

        const uint32_t* Awarp = AF + st * AFS2 + (wmi << 10);
        #pragma unroll
        for (int ks2 = 0; ks2 < 2; ks2++) {
            uint32_t af[4][4], bf[4][2];
            #pragma unroll
            for (int mt = 0; mt < 4; mt++) {
                uint4 a4 = *(const uint4*)(Awarp + (((ks2 * 4 + mt) * 32 + lane) << 2));
                af[mt][0] = a4.x; af[mt][1] = a4.y;
                af[mt][2] = a4.z; af[mt][3] = a4.w;
            }
            #pragma unroll
            for (int nt = 0; nt < 4; nt++) {
                bf[nt][0] = Bs[st][ks2 * 8 + tig][wn + nt * 8 + gid];
                bf[nt][1] = Bs[st][ks2 * 8 + tig + 4][wn + nt * 8 + gid];
            }
            #pragma unroll
            for (int mt = 0; mt < 4; mt++)
                #pragma unroll
                for (int nt = 0; nt < 4; nt++)
                    mma16h(acc[mt][nt], af[mt], bf[nt]);
        }

        if (it + 1 < niter) {
            SSTORE(st ^ 1);
            __syncthreads();
            st ^= 1;
        }
    }

    const int wm = wmi * 64;
    #pragma unroll
    for (int mt = 0; mt < 4; mt++) {
        #pragma unroll
        for (int half = 0; half < 2; half++) {
            int m = bm + wm + mt * 16 + gid + half * 8;
            #pragma unroll
            for (int nt = 0; nt < 4; nt++) {
                int n = bn + wn + nt * 8 + tig * 2;
                float2 v;
                v.x = acc[mt][nt][half * 2 + 0];
                v.y = acc[mt][nt][half * 2 + 1];
                if (EPI & 1) { v.x += bias[n]; v.y += bias[n + 1]; }
                if (EPI & 2) { v.x = fmaxf(v.x, 0.f); v.y = fmaxf(v.y, 0.f); }
                if (EPI & 4) {
                    float2 r = *(const float2*)&res[(size_t)m * N + n];
                    v.x += r.x; v.y += r.y;
                }
                *(float2*)&C[(size_t)m * N + n] = v;
            }
        }
    }
    #undef GLOAD
    #undef SSTORE
}

template <int EPI>
__global__ void __launch_bounds__(256)
gemm_tc(const float* __restrict__ A, const float* __restrict__ W,
        const float* __restrict__ bias, const float* __restrict__ res,
        float* __restrict__ C, int M, int N, int K)
{
    gemm_core<EPI>(A, W, bias, res, C, M, N, K);
}

struct QKVArgs { const float *w0, *w1, *w2; float *c0, *c1, *c2; };

__global__ void __launch_bounds__(256)
gemm_qkv(const float* __restrict__ A, QKVArgs p, int M, int N, int K)
{
    const float* W = (blockIdx.z == 0) ? p.w0 : (blockIdx.z == 1) ? p.w1 : p.w2;
    float*       C = (blockIdx.z == 0) ? p.c0 : (blockIdx.z == 1) ? p.c1 : p.c2;
    gemm_core<0>(A, W, nullptr, nullptr, C, M, N, K);
}

// ---------------- FA2 attention: split-fp16 S, fp16 PV, prefetch ----------
// Q tile 128/CTA, K tile 64. 8 warps own m16 x all 64 cols.
// S = QK^T via hi/lo fp16 (3x mma16h, err ~2^-20). Softmax in registers.
// K/V loaded to regs (prefetch), converted to smem half2; 1 sync per tile.
#define KP2 72                      // half2 row stride (words): bank permutation
#define ATT_TILE (32 * KP2)         // 2304 words per tile array
#define ATTN_SMEM (6 * ATT_TILE * 4)

__global__ void __launch_bounds__(256) attn_fa2_kernel()
{
    extern __shared__ uint32_t smA[];
    uint32_t* sKH = smA;                    // [2][ATT_TILE] K hi pairs
    uint32_t* sKL = smA + 2 * ATT_TILE;     // K lo pairs
    uint32_t* sVP = smA + 4 * ATT_TILE;     // V seq-pairs

    const int qi = (int)gridDim.x - 1 - (int)blockIdx.x;   // big tiles first
    const int h  = blockIdx.y, b = blockIdx.z;
    const int tid = threadIdx.x;
    const int lane = tid & 31, wid = tid >> 5;
    const int gid = lane >> 2, tig = lane & 3;
    const int r0  = wid * 16;
    const int hcol = h * HD_;

    const int row0g = qi * 128 + r0 + gid;
    const int row1g = row0g + 8;

    // ---- preload Q fragments (fp16 hi/lo split), 4 k16-steps
    uint32_t qH[4][4], qL[4][4];
    {
        size_t base0 = (size_t)(b * T_ + row0g) * D_ + hcol;
        size_t base1 = base0 + 8 * (size_t)D_;
        #pragma unroll
        for (int ks2 = 0; ks2 < 4; ks2++) {
            int ea = 2 * (ks2 * 8 + tig);
            int eb = ea + 8;
            float f[4][2] = {
                { g_q[base0 + ea], g_q[base0 + ea + 1] },
                { g_q[base1 + ea], g_q[base1 + ea + 1] },
                { g_q[base0 + eb], g_q[base0 + eb + 1] },
                { g_q[base1 + eb], g_q[base1 + eb + 1] } };
            #pragma unroll
            for (int w = 0; w < 4; w++) {
                __half h0 = __float2half_rn(f[w][0]);
                __half h1 = __float2half_rn(f[w][1]);
                float  l0 = f[w][0] - __half2float(h0);
                float  l1 = f[w][1] - __half2float(h1);
                qH[ks2][w] = h2u(__halves2half2(h0, h1));
                qL[ks2][w] = h2u(__floats2half2_rn(l0, l1));
            }
        }
    }

    float oacc[8][4];
    #pragma unroll
    for (int i = 0; i < 8; i++)
        #pragma unroll
        for (int j = 0; j < 4; j++) oacc[i][j] = 0.f;

    float m0 = -1e30f, m1 = -1e30f, l0s = 0.f, l1s = 0.f;
    const int ntk = 2 * qi + 2;

    float4 rk[4], rv0[2], rv1[2];

    // K: task (s = i&63, ep4 = i>>6): float4 over headdim -> rows 2ep4,2ep4+1
    #define ALOAD(kt)                                                        \
        do {                                                                 \
            _Pragma("unroll")                                                \
            for (int t = 0; t < 4; t++) {                                    \
                int i = tid + t * 256;                                       \
                int s = i & 63, ep4 = i >> 6;                                \
                rk[t] = *(const float4*)&g_k[(size_t)(b * T_ + (kt) * 64 + s) * D_ + hcol + 4 * ep4]; \
            }                                                                \
            _Pragma("unroll")                                                \
            for (int t = 0; t < 2; t++) {                                    \
                int i = tid + t * 256;                                       \
                int cp = i >> 4, e4 = i & 15;                                \
                size_t gb = (size_t)(b * T_ + (kt) * 64 + 2 * cp) * D_ + hcol + 4 * e4; \
                rv0[t] = *(const float4*)&g_v[gb];                           \
                rv1[t] = *(const float4*)&g_v[gb + D_];                      \
            }                                                                \
        } while (0)

    #define ASTORE(st)                                                       \
        do {                                                                 \
            _Pragma("unroll")                                                \
            for (int t = 0; t < 4; t++) {                                    \
                int i = tid + t * 256;                                       \
                int s = i & 63, ep4 = i >> 6;                                \
                __half hx = __float2half_rn(rk[t].x), hy = __float2half_rn(rk[t].y); \
                __half hz = __float2half_rn(rk[t].z), hw = __float2half_rn(rk[t].w); \
                float lx = rk[t].x - __half2float(hx), ly = rk[t].y - __half2float(hy); \
                float lz = rk[t].z - __half2float(hz), lw = rk[t].w - __half2float(hw); \
                sKH[(st) * ATT_TILE + (2 * ep4)     * KP2 + s] = h2u(__halves2half2(hx, hy)); \
                sKH[(st) * ATT_TILE + (2 * ep4 + 1) * KP2 + s] = h2u(__halves2half2(hz, hw)); \
                sKL[(st) * ATT_TILE + (2 * ep4)     * KP2 + s] = h2u(__floats2half2_rn(lx, ly)); \
                sKL[(st) * ATT_TILE + (2 * ep4 + 1) * KP2 + s] = h2u(__floats2half2_rn(lz, lw)); \
            }                                                                \
            _Pragma("unroll")                                                \
            for (int t = 0; t < 2; t++) {                                    \
                int i = tid + t * 256;                                       \
                int cp = i >> 4, e4 = i & 15;                                \
                uint4 u;                                                     \
                u.x = h2u(__floats2half2_rn(rv0[t].x, rv1[t].x));            \
                u.y = h2u(__floats2half2_rn(rv0[t].y, rv1[t].y));            \
                u.z = h2u(__floats2half2_rn(rv0[t].z, rv1[t].z));            \
                u.w = h2u(__floats2half2_rn(rv0[t].w, rv1[t].w));            \
                *(uint4*)&sVP[(st) * ATT_TILE + cp * KP2 + 4 * e4] = u;      \
            }                                                                \
        } while (0)

    ALOAD(0);
    ASTORE(0);
    __syncthreads();

    int st = 0;
    for (int kt = 0; kt < ntk; kt++) {
        if (kt + 1 < ntk) ALOAD(kt + 1);

        const uint32_t* KHs = sKH + st * ATT_TILE;
        const uint32_t* KLs = sKL + st * ATT_TILE;
        const uint32_t* VPs = sVP + st * ATT_TILE;

        // ---- S = Q K^T (split fp16)
        float sa[8][4];
        #pragma unroll
        for (int i = 0; i < 8; i++)
            #pragma unroll
            for (int j = 0; j < 4; j++) sa[i][j] = 0.f;

        #pragma unroll
        for (int ks2 = 0; ks2 < 4; ks2++) {
            int kpa = (ks2 * 8 + tig) * KP2, kpb = (ks2 * 8 + tig + 4) * KP2;
            #pragma unroll
            for (int nt = 0; nt < 8; nt++) {
                int n = nt * 8 + gid;
                uint32_t bH[2] = { KHs[kpa + n], KHs[kpb + n] };
                uint32_t bL[2] = { KLs[kpa + n], KLs[kpb + n] };
                mma16h(sa[nt], qH[ks2], bH);
                mma16h(sa[nt], qL[ks2], bH);
                mma16h(sa[nt], qH[ks2], bL);
            }
        }

        // ---- scale + causal mask
        bool diag = (kt >= 2 * qi);
        #pragma unroll
        for (int nt = 0; nt < 8; nt++) {
            int cg = kt * 64 + nt * 8 + tig * 2;
            sa[nt][0] *= 0.125f; sa[nt][1] *= 0.125f;
            sa[nt][2] *= 0.125f; sa[nt][3] *= 0.125f;
            if (diag) {
                if (cg     > row0g) sa[nt][0] = -1e30f;
                if (cg + 1 > row0g) sa[nt][1] = -1e30f;
                if (cg     > row1g) sa[nt][2] = -1e30f;
                if (cg + 1 > row1g) sa[nt][3] = -1e30f;
            }
        }

        // ---- online softmax (registers + quad shfl)
        float mx0 = -1e30f, mx1 = -1e30f;
        #pragma unroll
        for (int nt = 0; nt < 8; nt++) {
            mx0 = fmaxf(mx0, fmaxf(sa[nt][0], sa[nt][1]));
            mx1 = fmaxf(mx1, fmaxf(sa[nt][2], sa[nt][3]));
        }
        mx0 = fmaxf(mx0, __shfl_xor_sync(0xffffffffu, mx0, 1));
        mx0 = fmaxf(mx0, __shfl_xor_sync(0xffffffffu, mx0, 2));
        mx1 = fmaxf(mx1, __shfl_xor_sync(0xffffffffu, mx1, 1));
        mx1 = fmaxf(mx1, __shfl_xor_sync(0xffffffffu, mx1, 2));
        float mn0 = fmaxf(m0, mx0), mn1 = fmaxf(m1, mx1);
        float al0 = __expf(m0 - mn0), al1 = __expf(m1 - mn1);
        m0 = mn0; m1 = mn1;

        float s0 = 0.f, s1 = 0.f;
        uint32_t pf[8][2];
        #pragma unroll
        for (int nt = 0; nt < 8; nt++) {
            float p0 = __expf(sa[nt][0] - mn0);
            float p1 = __expf(sa[nt][1] - mn0);
            float p2 = __expf(sa[nt][2] - mn1);
            float p3 = __expf(sa[nt][3] - mn1);
            s0 += p0 + p1; s1 += p2 + p3;
            pf[nt][0] = h2u(__floats2half2_rn(p0, p1));
            pf[nt][1] = h2u(__floats2half2_rn(p2, p3));
        }
        s0 += __shfl_xor_sync(0xffffffffu, s0, 1);
        s0 += __shfl_xor_sync(0xffffffffu, s0, 2);
        s1 += __shfl_xor_sync(0xffffffffu, s1, 1);
        s1 += __shfl_xor_sync(0xffffffffu, s1, 2);
        l0s = l0s * al0 + s0;
        l1s = l1s * al1 + s1;

        #pragma unroll
        for (int nt = 0; nt < 8; nt++) {
            oacc[nt][0] *= al0; oacc[nt][1] *= al0;
            oacc[nt][2] *= al1; oacc[nt][3] *= al1;
        }

        // ---- O += P V (fp16, P from registers: S c-frag == PV a-frag)
        #pragma unroll
        for (int ks2 = 0; ks2 < 4; ks2++) {
            uint32_t af[4] = { pf[2 * ks2][0], pf[2 * ks2][1],
                               pf[2 * ks2 + 1][0], pf[2 * ks2 + 1][1] };
            int kpa = (ks2 * 8 + tig) * KP2, kpb = (ks2 * 8 + tig + 4) * KP2;
            #pragma unroll
            for (int nt = 0; nt < 8; nt++) {
                int n = nt * 8 + gid;
                uint32_t bf[2] = { VPs[kpa + n], VPs[kpb + n] };
                mma16h(oacc[nt], af, bf);
            }
        }

        if (kt + 1 < ntk) {
            ASTORE(st ^ 1);
            __syncthreads();
            st ^= 1;
        }
    }
    #undef ALOAD
    #undef ASTORE

    // ---- write O / l
    {
        float inv0 = 1.0f / l0s, inv1 = 1.0f / l1s;
        size_t b0 = (size_t)(b * T_ + row0g) * D_ + hcol;
        size_t b1 = (size_t)(b * T_ + row1g) * D_ + hcol;
        #pragma unroll
        for (int nt = 0; nt < 8; nt++) {
            int cb = nt * 8 + tig * 2;
            *(float2*)&g_ao[b0 + cb] = make_float2(oacc[nt][0] * inv0, oacc[nt][1] * inv0);
            *(float2*)&g_ao[b1 + cb] = make_float2(oacc[nt][2] * inv1, oacc[nt][3] * inv1);
        }
    }
}

// ---------------- host side ----------------------------------------------
static void launch_gemm(const float* A, const float* W, const float* bias,
                        const float* res, float* C, int M, int N, int K, int epi)
{
    dim3 grid(N / GBN, M / GBM), blk(256);
    switch (epi) {
        case 0: gemm_tc<0><<<grid, blk, GEMM_SMEM>>>(A, W, nullptr, nullptr, C, M, N, K); break;
        case 1: gemm_tc<1><<<grid, blk, GEMM_SMEM>>>(A, W, bias,    nullptr, C, M, N, K); break;
        case 3: gemm_tc<3><<<grid, blk, GEMM_SMEM>>>(A, W, bias,    nullptr, C, M, N, K); break;
        case 5: gemm_tc<5><<<grid, blk, GEMM_SMEM>>>(A, W, bias,    res,     C, M, N, K); break;
    }
}

extern "C" void kernel_launch(void* const* d_in, const int* in_sizes, int n_in,
                              void* d_out, int out_size)
{
    const int*   ctx  = (const int*)  d_in[0];
    const float* tok  = (const float*)d_in[1];
    const float* pos  = (const float*)d_in[2];
    const float* Wq   = (const float*)d_in[3];
    const float* Wk   = (const float*)d_in[4];
    const float* Wv   = (const float*)d_in[5];
    const float* Wo   = (const float*)d_in[6];
    const float* bo   = (const float*)d_in[7];
    const float* ln1s = (const float*)d_in[8];
    const float* ln1b = (const float*)d_in[9];
    const float* W1   = (const float*)d_in[10];
    const float* b1   = (const float*)d_in[11];
    const float* W2   = (const float*)d_in[12];
    const float* b2   = (const float*)d_in[13];
    const float* ln2s = (const float*)d_in[14];
    const float* ln2b = (const float*)d_in[15];
    const float* lnfs = (const float*)d_in[16];
    const float* lnfb = (const float*)d_in[17];
    const float* Wout = (const float*)d_in[18];
    const float* bout = (const float*)d_in[19];
    float* out = (float*)d_out;

    float *x, *h, *q, *k, *v, *ao, *ff;
    cudaGetSymbolAddress((void**)&x,  g_x);
    cudaGetSymbolAddress((void**)&h,  g_h);
    cudaGetSymbolAddress((void**)&q,  g_q);
    cudaGetSymbolAddress((void**)&k,  g_k);
    cudaGetSymbolAddress((void**)&v,  g_v);
    cudaGetSymbolAddress((void**)&ao, g_ao);
    cudaGetSymbolAddress((void**)&ff, g_ff);

    cudaFuncSetAttribute(attn_fa2_kernel,
                         cudaFuncAttributeMaxDynamicSharedMemorySize, ATTN_SMEM);
    cudaFuncSetAttribute(gemm_tc<0>, cudaFuncAttributeMaxDynamicSharedMemorySize, GEMM_SMEM);
    cudaFuncSetAttribute(gemm_tc<1>, cudaFuncAttributeMaxDynamicSharedMemorySize, GEMM_SMEM);
    cudaFuncSetAttribute(gemm_tc<3>, cudaFuncAttributeMaxDynamicSharedMemorySize, GEMM_SMEM);
    cudaFuncSetAttribute(gemm_tc<5>, cudaFuncAttributeMaxDynamicSharedMemorySize, GEMM_SMEM);
    cudaFuncSetAttribute(gemm_qkv,   cudaFuncAttributeMaxDynamicSharedMemorySize, GEMM_SMEM);

    embed_kernel<<<BT * D_ / 1024, 256>>>(ctx, (const float4*)tok, (const float4*)pos);

    for (int l = 0; l < L_; l++) {
        ln_kernel<<<BT, 256>>>(x, ln1s + (size_t)l * D_, ln1b + (size_t)l * D_, h);
        QKVArgs p { Wq + (size_t)l * D_ * D_, Wk + (size_t)l * D_ * D_,
                    Wv + (size_t)l * D_ * D_, q, k, v };
        gemm_qkv<<<dim3(D_ / GBN, BT / GBM, 3), 256, GEMM_SMEM>>>(h, p, BT, D_, D_);
        attn_fa2_kernel<<<dim3(T_ / 128, H_, Bz), 256, ATTN_SMEM>>>();
        launch_gemm(ao, Wo + (size_t)l * D_ * D_, bo + (size_t)l * D_, x, x, BT, D_, D_, 5);
        ln_kernel<<<BT, 256>>>(x, ln2s + (size_t)l * D_, ln2b + (size_t)l * D_, h);
        launch_gemm(h, W1 + (size_t)l * D_ * FF_, b1 + (size_t)l * FF_, nullptr, ff, BT, FF_, D_, 3);
        launch_gemm(ff, W2 + (size_t)l * FF_ * D_, b2 + (size_t)l * D_, x, x, BT, D_, FF_, 5);
    }
    ln_kernel<<<BT, 256>>>(x, lnfs, lnfb, h);
    launch_gemm(h, Wout, bout, nullptr, out, BT, V_, D_, 1);
}